// round 4
// baseline (speedup 1.0000x reference)
#include <cuda_runtime.h>
#include <cuda_fp16.h>
#include <cstdint>

#define NN 100000
#define EE 800000
#define HEADS 8
#define CH 16
#define DIM 128
#define NEG_SLOPE 0.2f

// ---------------- scratch (device globals; no allocation allowed) -------------
__device__ float  g_h_in[NN * DIM];
__device__ float  g_h_out[NN * DIM];
__device__ __half g_h_in_h[NN * DIM];
__device__ __half g_h_out_h[NN * DIM];
__device__ float  g_asrc_in[NN * HEADS];
__device__ float  g_adst_in[NN * HEADS];
__device__ float  g_asrc_out[NN * HEADS];
__device__ float  g_adst_out[NN * HEADS];
__device__ float  g_den_in[NN * HEADS];
__device__ float  g_den_out[NN * HEADS];

// ---------------- helpers ------------------------------------------------------
__device__ __forceinline__ void red_add_v4(float* p, float a, float b, float c, float d) {
    asm volatile("red.global.add.v4.f32 [%0], {%1, %2, %3, %4};"
                 :: "l"(p), "f"(a), "f"(b), "f"(c), "f"(d) : "memory");
}

__device__ __forceinline__ float lrelu(float v) {
    return v > 0.0f ? v : NEG_SLOPE * v;
}

// ---------------- init kernels -------------------------------------------------
__global__ void init_out_kernel(float* __restrict__ out,
                                const float* __restrict__ b_in,
                                const float* __restrict__ b_out) {
    int t = blockIdx.x * blockDim.x + threadIdx.x;
    if (t >= NN * DIM) return;
    int c = t & (DIM - 1);
    out[t] = b_in[c] + b_out[c];
}

__global__ void zero_denoms_kernel() {
    int t = blockIdx.x * blockDim.x + threadIdx.x;
    if (t >= NN * HEADS) return;
    g_den_in[t] = 0.0f;
    g_den_out[t] = 0.0f;
}

// ---------------- GEMM: C[M,128] = A[M,128] @ B[128,128], double-buffered -------
// BM=128, BN=128, BK=16, 256 threads, 8x8 micro-tile, smem ping-pong.
// Epilogue writes fp32 C and an fp16 copy Ch.
__global__ __launch_bounds__(256, 2)
void gemm128_db_kernel(const float* __restrict__ A, const float* __restrict__ B,
                       float* __restrict__ C, __half* __restrict__ Ch, int M) {
    __shared__ float As[2][16][128];   // [buf][k][m]
    __shared__ float Bs[2][16][128];   // [buf][k][n]

    int tid = threadIdx.x;
    int tx = tid & 15;       // 0..15 -> col groups
    int ty = tid >> 4;       // 0..15 -> row groups
    int row0 = blockIdx.x * 128;

    int ar = tid >> 2;            // 0..63
    int ac = (tid & 3) * 4;       // 0,4,8,12
    int br = tid >> 5;            // 0..7
    int bc = (tid & 31) * 4;      // 0..124

    float acc[8][8];
#pragma unroll
    for (int i = 0; i < 8; i++)
#pragma unroll
        for (int j = 0; j < 8; j++) acc[i][j] = 0.0f;

    // prologue: tile 0 -> buffer 0
#pragma unroll
    for (int rr = 0; rr < 2; rr++) {
        int r = ar + rr * 64;
        float4 v = make_float4(0.f, 0.f, 0.f, 0.f);
        if (row0 + r < M) v = *(const float4*)&A[(size_t)(row0 + r) * DIM + ac];
        As[0][ac + 0][r] = v.x;
        As[0][ac + 1][r] = v.y;
        As[0][ac + 2][r] = v.z;
        As[0][ac + 3][r] = v.w;
    }
#pragma unroll
    for (int rr = 0; rr < 2; rr++) {
        int r = br + rr * 8;
        *(float4*)&Bs[0][r][bc] = *(const float4*)&B[(size_t)r * DIM + bc];
    }
    __syncthreads();

    int buf = 0;
#pragma unroll
    for (int k0 = 0; k0 < 8; k0++) {
        float4 ra[2], rb[2];
        if (k0 < 7) {
            int kk = (k0 + 1) * 16;
#pragma unroll
            for (int rr = 0; rr < 2; rr++) {
                int r = ar + rr * 64;
                ra[rr] = make_float4(0.f, 0.f, 0.f, 0.f);
                if (row0 + r < M)
                    ra[rr] = *(const float4*)&A[(size_t)(row0 + r) * DIM + kk + ac];
            }
#pragma unroll
            for (int rr = 0; rr < 2; rr++) {
                int r = br + rr * 8;
                rb[rr] = *(const float4*)&B[(size_t)(kk + r) * DIM + bc];
            }
        }

#pragma unroll
        for (int k = 0; k < 16; k++) {
            float a[8], b[8];
            *(float4*)&a[0] = *(const float4*)&As[buf][k][ty * 8];
            *(float4*)&a[4] = *(const float4*)&As[buf][k][ty * 8 + 4];
            *(float4*)&b[0] = *(const float4*)&Bs[buf][k][tx * 8];
            *(float4*)&b[4] = *(const float4*)&Bs[buf][k][tx * 8 + 4];
#pragma unroll
            for (int i = 0; i < 8; i++)
#pragma unroll
                for (int j = 0; j < 8; j++) acc[i][j] += a[i] * b[j];
        }

        if (k0 < 7) {
            int nb = buf ^ 1;
#pragma unroll
            for (int rr = 0; rr < 2; rr++) {
                int r = ar + rr * 64;
                As[nb][ac + 0][r] = ra[rr].x;
                As[nb][ac + 1][r] = ra[rr].y;
                As[nb][ac + 2][r] = ra[rr].z;
                As[nb][ac + 3][r] = ra[rr].w;
            }
#pragma unroll
            for (int rr = 0; rr < 2; rr++) {
                int r = br + rr * 8;
                *(float4*)&Bs[nb][r][bc] = rb[rr];
            }
            __syncthreads();
            buf = nb;
        }
    }

    // epilogue: fp32 + fp16 copies
#pragma unroll
    for (int i = 0; i < 8; i++) {
        int r = row0 + ty * 8 + i;
        if (r < M) {
            *(float4*)&C[(size_t)r * DIM + tx * 8] =
                make_float4(acc[i][0], acc[i][1], acc[i][2], acc[i][3]);
            *(float4*)&C[(size_t)r * DIM + tx * 8 + 4] =
                make_float4(acc[i][4], acc[i][5], acc[i][6], acc[i][7]);
            __half2 p0 = __floats2half2_rn(acc[i][0], acc[i][1]);
            __half2 p1 = __floats2half2_rn(acc[i][2], acc[i][3]);
            __half2 p2 = __floats2half2_rn(acc[i][4], acc[i][5]);
            __half2 p3 = __floats2half2_rn(acc[i][6], acc[i][7]);
            uint4 pk;
            pk.x = *reinterpret_cast<unsigned*>(&p0);
            pk.y = *reinterpret_cast<unsigned*>(&p1);
            pk.z = *reinterpret_cast<unsigned*>(&p2);
            pk.w = *reinterpret_cast<unsigned*>(&p3);
            *(uint4*)&Ch[(size_t)r * DIM + tx * 8] = pk;
        }
    }
}

// ---------------- per-node attention logits (fp32 h, exact) ---------------------
__global__ void alpha_kernel(const float* __restrict__ a_src_in,
                             const float* __restrict__ a_dst_in,
                             const float* __restrict__ a_src_out,
                             const float* __restrict__ a_dst_out) {
    int t = blockIdx.x * blockDim.x + threadIdx.x;
    if (t >= NN * HEADS) return;
    int n = t >> 3;
    int hd = t & 7;

    const float4* hi = (const float4*)&g_h_in[(size_t)n * DIM + hd * CH];
    const float4* ho = (const float4*)&g_h_out[(size_t)n * DIM + hd * CH];
    const float4* wsi = (const float4*)&a_src_in[hd * CH];
    const float4* wdi = (const float4*)&a_dst_in[hd * CH];
    const float4* wso = (const float4*)&a_src_out[hd * CH];
    const float4* wdo = (const float4*)&a_dst_out[hd * CH];

    float si = 0.f, di = 0.f, so = 0.f, dof = 0.f;
#pragma unroll
    for (int q = 0; q < 4; q++) {
        float4 v = hi[q];
        float4 w1 = wsi[q];
        float4 w2 = wdi[q];
        si += v.x * w1.x + v.y * w1.y + v.z * w1.z + v.w * w1.w;
        di += v.x * w2.x + v.y * w2.y + v.z * w2.z + v.w * w2.w;
        float4 u = ho[q];
        float4 w3 = wso[q];
        float4 w4 = wdo[q];
        so += u.x * w3.x + u.y * w3.y + u.z * w3.z + u.w * w3.w;
        dof += u.x * w4.x + u.y * w4.y + u.z * w4.z + u.w * w4.w;
    }
    g_asrc_in[t] = si;
    g_adst_in[t] = di;
    g_asrc_out[t] = so;
    g_adst_out[t] = dof;
}

// ---------------- softmax denominators (shift-invariant) ------------------------
__global__ void denom_kernel(const int* __restrict__ ei) {
    int t = blockIdx.x * blockDim.x + threadIdx.x;
    if (t >= EE * HEADS) return;
    int e = t >> 3;
    int hd = t & 7;
    int s = __ldg(&ei[e]);
    int d = __ldg(&ei[EE + e]);

    float li = lrelu(g_asrc_in[s * HEADS + hd] + g_adst_in[d * HEADS + hd]);
    atomicAdd(&g_den_in[d * HEADS + hd], __expf(li));

    float lo = lrelu(g_asrc_out[d * HEADS + hd] + g_adst_out[s * HEADS + hd]);
    atomicAdd(&g_den_out[s * HEADS + hd], __expf(lo));
}

// ---------------- aggregation: 16 lanes/edge, fp16 gathers, fp32 atomics --------
__global__ __launch_bounds__(256)
void agg_kernel(const int* __restrict__ ei, float* __restrict__ out) {
    int gt = blockIdx.x * blockDim.x + threadIdx.x;
    int e = gt >> 4;
    if (e >= EE) return;
    int lane = threadIdx.x & 15;
    int hd = lane >> 1;           // head for this lane's 8 channels
    int s = __ldg(&ei[e]);
    int d = __ldg(&ei[EE + e]);

    float li = lrelu(g_asrc_in[s * HEADS + hd] + g_adst_in[d * HEADS + hd]);
    float ci = __expf(li) * __frcp_rn(g_den_in[d * HEADS + hd]);

    float lo = lrelu(g_asrc_out[d * HEADS + hd] + g_adst_out[s * HEADS + hd]);
    float co = __expf(lo) * __frcp_rn(g_den_out[s * HEADS + hd]);

    int c8 = lane * 8;
    uint4 ui = *(const uint4*)&g_h_in_h[(size_t)s * DIM + c8];
    uint4 uo = *(const uint4*)&g_h_out_h[(size_t)d * DIM + c8];

    float2 i0 = __half22float2(*reinterpret_cast<__half2*>(&ui.x));
    float2 i1 = __half22float2(*reinterpret_cast<__half2*>(&ui.y));
    float2 i2 = __half22float2(*reinterpret_cast<__half2*>(&ui.z));
    float2 i3 = __half22float2(*reinterpret_cast<__half2*>(&ui.w));
    float2 o0 = __half22float2(*reinterpret_cast<__half2*>(&uo.x));
    float2 o1 = __half22float2(*reinterpret_cast<__half2*>(&uo.y));
    float2 o2 = __half22float2(*reinterpret_cast<__half2*>(&uo.z));
    float2 o3 = __half22float2(*reinterpret_cast<__half2*>(&uo.w));

    float* pd = &out[(size_t)d * DIM + c8];
    red_add_v4(pd,     i0.x * ci, i0.y * ci, i1.x * ci, i1.y * ci);
    red_add_v4(pd + 4, i2.x * ci, i2.y * ci, i3.x * ci, i3.y * ci);

    float* ps = &out[(size_t)s * DIM + c8];
    red_add_v4(ps,     o0.x * co, o0.y * co, o1.x * co, o1.y * co);
    red_add_v4(ps + 4, o2.x * co, o2.y * co, o3.x * co, o3.y * co);
}

// ---------------- launch --------------------------------------------------------
extern "C" void kernel_launch(void* const* d_in, const int* in_sizes, int n_in,
                              void* d_out, int out_size) {
    const float* x        = (const float*)d_in[0];
    const int*   ei       = (const int*)d_in[1];
    const float* W_in     = (const float*)d_in[2];
    const float* a_src_in = (const float*)d_in[3];
    const float* a_dst_in = (const float*)d_in[4];
    const float* b_in     = (const float*)d_in[5];
    const float* W_out    = (const float*)d_in[6];
    const float* a_src_out= (const float*)d_in[7];
    const float* a_dst_out= (const float*)d_in[8];
    const float* b_out    = (const float*)d_in[9];
    float* out = (float*)d_out;

    float*  h_in;
    float*  h_out;
    __half* h_in_h;
    __half* h_out_h;
    cudaGetSymbolAddress((void**)&h_in,    g_h_in);
    cudaGetSymbolAddress((void**)&h_out,   g_h_out);
    cudaGetSymbolAddress((void**)&h_in_h,  g_h_in_h);
    cudaGetSymbolAddress((void**)&h_out_h, g_h_out_h);

    // init output with biases; zero softmax denominators
    init_out_kernel<<<(NN * DIM + 255) / 256, 256>>>(out, b_in, b_out);
    zero_denoms_kernel<<<(NN * HEADS + 255) / 256, 256>>>();

    // projections (fp32 + fp16 copies)
    gemm128_db_kernel<<<(NN + 127) / 128, 256>>>(x, W_in,  h_in,  h_in_h,  NN);
    gemm128_db_kernel<<<(NN + 127) / 128, 256>>>(x, W_out, h_out, h_out_h, NN);

    // per-node logits (fp32, exact)
    alpha_kernel<<<(NN * HEADS + 255) / 256, 256>>>(a_src_in, a_dst_in, a_src_out, a_dst_out);

    // softmax denominators (one edge pass, both directions)
    denom_kernel<<<(EE * HEADS + 255) / 256, 256>>>(ei);

    // weighted aggregation (one edge pass, both directions, fp16 gathers)
    agg_kernel<<<(EE * 16 + 255) / 256, 256>>>(ei, out);
}

// round 5
// speedup vs baseline: 1.4907x; 1.4907x over previous
#include <cuda_runtime.h>
#include <cuda_fp16.h>
#include <cstdint>

#define NN 100000
#define EE 800000
#define HEADS 8
#define CH 16
#define DIM 128
#define NEG_SLOPE 0.2f

#define NN2 (2 * NN)          // concatenated [in-counts | out-counts]
#define SCAN_CHUNK 2048       // elems per scan block (256 thr * 8)
#define NB_SCAN ((NN2 + SCAN_CHUNK - 1) / SCAN_CHUNK)   // 98

// ---------------- scratch (device globals; no allocation allowed) -------------
__device__ float  g_h_in[NN * DIM];
__device__ float  g_h_out[NN * DIM];
__device__ __half g_h_in_h[NN * DIM];
__device__ __half g_h_out_h[NN * DIM];
__device__ float  g_asrc_in[NN * HEADS];
__device__ float  g_adst_in[NN * HEADS];
__device__ float  g_asrc_out[NN * HEADS];
__device__ float  g_adst_out[NN * HEADS];

__device__ int    g_cnt[NN2];
__device__ int    g_cur[NN2];
__device__ int    g_off[NN2 + 1];
__device__ int    g_bsum[128];
__device__ int    g_nbr[2 * EE];   // [0,EE): in-dir neighbors (src, grouped by dst)
                                   // [EE,2EE): out-dir neighbors (dst, grouped by src)

// ---------------- helpers ------------------------------------------------------
__device__ __forceinline__ float lrelu(float v) {
    return v > 0.0f ? v : NEG_SLOPE * v;
}

// ---------------- CSR build ----------------------------------------------------
__global__ void zero_cnt_kernel() {
    int t = blockIdx.x * blockDim.x + threadIdx.x;
    if (t < NN2) { g_cnt[t] = 0; g_cur[t] = 0; }
}

__global__ void hist_kernel(const int* __restrict__ ei) {
    int e = blockIdx.x * blockDim.x + threadIdx.x;
    if (e >= EE) return;
    int s = __ldg(&ei[e]);
    int d = __ldg(&ei[EE + e]);
    atomicAdd(&g_cnt[d], 1);          // in-direction grouped by dst
    atomicAdd(&g_cnt[NN + s], 1);     // out-direction grouped by src
}

__global__ void scan1_kernel() {
    __shared__ int sh[256];
    int b = blockIdx.x;
    int t = threadIdx.x;
    int base = b * SCAN_CHUNK + t * 8;
    int v[8];
    int s = 0;
#pragma unroll
    for (int k = 0; k < 8; k++) {
        int idx = base + k;
        v[k] = (idx < NN2) ? g_cnt[idx] : 0;
        s += v[k];
    }
    sh[t] = s;
    __syncthreads();
#pragma unroll
    for (int off = 1; off < 256; off <<= 1) {
        int x = (t >= off) ? sh[t - off] : 0;
        __syncthreads();
        if (t >= off) sh[t] += x;
        __syncthreads();
    }
    int excl = sh[t] - s;
    if (t == 255) g_bsum[b] = sh[t];
    int run = excl;
#pragma unroll
    for (int k = 0; k < 8; k++) {
        int idx = base + k;
        if (idx < NN2) g_off[idx] = run;
        run += v[k];
    }
}

__global__ void scan2_kernel() {
    __shared__ int sh[128];
    int t = threadIdx.x;
    int s = (t < NB_SCAN) ? g_bsum[t] : 0;
    sh[t] = s;
    __syncthreads();
#pragma unroll
    for (int off = 1; off < 128; off <<= 1) {
        int x = (t >= off) ? sh[t - off] : 0;
        __syncthreads();
        if (t >= off) sh[t] += x;
        __syncthreads();
    }
    g_bsum[t] = sh[t] - s;   // exclusive
}

__global__ void scan3_kernel() {
    int t = blockIdx.x * blockDim.x + threadIdx.x;
    if (t < NN2) g_off[t] += g_bsum[t / SCAN_CHUNK];
    if (t == 0) g_off[NN2] = 2 * EE;
}

__global__ void scatter_kernel(const int* __restrict__ ei) {
    int e = blockIdx.x * blockDim.x + threadIdx.x;
    if (e >= EE) return;
    int s = __ldg(&ei[e]);
    int d = __ldg(&ei[EE + e]);
    int p0 = g_off[d] + atomicAdd(&g_cur[d], 1);
    g_nbr[p0] = s;
    int p1 = g_off[NN + s] + atomicAdd(&g_cur[NN + s], 1);
    g_nbr[p1] = d;
}

// ---------------- GEMM: C[M,128] = A[M,128] @ B[128,128] (R3 version + fp16) ----
__global__ __launch_bounds__(256, 2)
void gemm128_kernel(const float* __restrict__ A, const float* __restrict__ B,
                    float* __restrict__ C, __half* __restrict__ Ch, int M) {
    __shared__ float As[16][128];   // [k][m]
    __shared__ float Bs[16][128];   // [k][n]

    int tid = threadIdx.x;
    int tx = tid & 15;
    int ty = tid >> 4;
    int row0 = blockIdx.x * 128;

    float acc[8][8];
#pragma unroll
    for (int i = 0; i < 8; i++)
#pragma unroll
        for (int j = 0; j < 8; j++) acc[i][j] = 0.0f;

    for (int k0 = 0; k0 < 128; k0 += 16) {
        int ar = tid >> 2;
        int ac = (tid & 3) * 4;
#pragma unroll
        for (int rr = 0; rr < 2; rr++) {
            int r = ar + rr * 64;
            float4 v = make_float4(0.f, 0.f, 0.f, 0.f);
            if (row0 + r < M)
                v = *(const float4*)&A[(size_t)(row0 + r) * DIM + k0 + ac];
            As[ac + 0][r] = v.x;
            As[ac + 1][r] = v.y;
            As[ac + 2][r] = v.z;
            As[ac + 3][r] = v.w;
        }
        int br = tid >> 5;
        int bc = (tid & 31) * 4;
#pragma unroll
        for (int rr = 0; rr < 2; rr++) {
            int r = br + rr * 8;
            *(float4*)&Bs[r][bc] = *(const float4*)&B[(size_t)(k0 + r) * DIM + bc];
        }
        __syncthreads();

#pragma unroll
        for (int k = 0; k < 16; k++) {
            float a[8], b[8];
#pragma unroll
            for (int i = 0; i < 8; i++) a[i] = As[k][ty * 8 + i];
#pragma unroll
            for (int j = 0; j < 8; j++) b[j] = Bs[k][tx * 8 + j];
#pragma unroll
            for (int i = 0; i < 8; i++)
#pragma unroll
                for (int j = 0; j < 8; j++) acc[i][j] += a[i] * b[j];
        }
        __syncthreads();
    }

#pragma unroll
    for (int i = 0; i < 8; i++) {
        int r = row0 + ty * 8 + i;
        if (r < M) {
            *(float4*)&C[(size_t)r * DIM + tx * 8] =
                make_float4(acc[i][0], acc[i][1], acc[i][2], acc[i][3]);
            *(float4*)&C[(size_t)r * DIM + tx * 8 + 4] =
                make_float4(acc[i][4], acc[i][5], acc[i][6], acc[i][7]);
            __half2 p0 = __floats2half2_rn(acc[i][0], acc[i][1]);
            __half2 p1 = __floats2half2_rn(acc[i][2], acc[i][3]);
            __half2 p2 = __floats2half2_rn(acc[i][4], acc[i][5]);
            __half2 p3 = __floats2half2_rn(acc[i][6], acc[i][7]);
            uint4 pk;
            pk.x = *reinterpret_cast<unsigned*>(&p0);
            pk.y = *reinterpret_cast<unsigned*>(&p1);
            pk.z = *reinterpret_cast<unsigned*>(&p2);
            pk.w = *reinterpret_cast<unsigned*>(&p3);
            *(uint4*)&Ch[(size_t)r * DIM + tx * 8] = pk;
        }
    }
}

// ---------------- per-node attention logits (fp32, exact) -----------------------
__global__ void alpha_kernel(const float* __restrict__ a_src_in,
                             const float* __restrict__ a_dst_in,
                             const float* __restrict__ a_src_out,
                             const float* __restrict__ a_dst_out) {
    int t = blockIdx.x * blockDim.x + threadIdx.x;
    if (t >= NN * HEADS) return;
    int n = t >> 3;
    int hd = t & 7;

    const float4* hi = (const float4*)&g_h_in[(size_t)n * DIM + hd * CH];
    const float4* ho = (const float4*)&g_h_out[(size_t)n * DIM + hd * CH];
    const float4* wsi = (const float4*)&a_src_in[hd * CH];
    const float4* wdi = (const float4*)&a_dst_in[hd * CH];
    const float4* wso = (const float4*)&a_src_out[hd * CH];
    const float4* wdo = (const float4*)&a_dst_out[hd * CH];

    float si = 0.f, di = 0.f, so = 0.f, dof = 0.f;
#pragma unroll
    for (int q = 0; q < 4; q++) {
        float4 v = hi[q];
        float4 w1 = wsi[q];
        float4 w2 = wdi[q];
        si += v.x * w1.x + v.y * w1.y + v.z * w1.z + v.w * w1.w;
        di += v.x * w2.x + v.y * w2.y + v.z * w2.z + v.w * w2.w;
        float4 u = ho[q];
        float4 w3 = wso[q];
        float4 w4 = wdo[q];
        so += u.x * w3.x + u.y * w3.y + u.z * w3.z + u.w * w3.w;
        dof += u.x * w4.x + u.y * w4.y + u.z * w4.z + u.w * w4.w;
    }
    g_asrc_in[t] = si;
    g_adst_in[t] = di;
    g_asrc_out[t] = so;
    g_adst_out[t] = dof;
}

// ---------------- aggregation: warp per node, gather-side, no output atomics ----
__global__ __launch_bounds__(256)
void agg_kernel(float* __restrict__ out,
                const float* __restrict__ b_in,
                const float* __restrict__ b_out) {
    int w = (blockIdx.x * blockDim.x + threadIdx.x) >> 5;
    if (w >= NN) return;
    int n = w;
    int lane = threadIdx.x & 31;
    unsigned FULL = 0xFFFFFFFFu;

    int c4 = lane * 4;                 // this lane's 4 output channels
    int hd4 = lane >> 2;               // head of those channels
    int hd8 = lane & 7;                // head this lane owns in denom pass

    float4 bi = *(const float4*)&b_in[c4];
    float4 bo = *(const float4*)&b_out[c4];
    float acc0 = bi.x + bo.x, acc1 = bi.y + bo.y;
    float acc2 = bi.z + bo.z, acc3 = bi.w + bo.w;

#pragma unroll
    for (int dir = 0; dir < 2; dir++) {
        const float*  asrc = dir ? g_asrc_out : g_asrc_in;   // indexed by neighbor
        const float*  adst = dir ? g_adst_out : g_adst_in;   // indexed by owner n
        const __half* hh   = dir ? g_h_out_h  : g_h_in_h;

        int base = g_off[dir * NN + n];
        int deg  = g_off[dir * NN + n + 1] - base;

        // ---- pass 1: softmax denominator per head (shift-invariant, no max) ----
        float adst_l = adst[n * HEADS + hd8];
        float den = 0.0f;
        for (int j = (lane >> 3); j < deg; j += 4) {         // 4 edges in flight
            int s = g_nbr[base + j];
            float li = lrelu(__ldg(&asrc[s * HEADS + hd8]) + adst_l);
            den += __expf(li);
        }
        den += __shfl_xor_sync(FULL, den, 8);
        den += __shfl_xor_sync(FULL, den, 16);
        float rden = __frcp_rn(den);                         // keyed by hd8

        // align per-head values to this lane's channel head
        float rden_h = __shfl_sync(FULL, rden, hd4);
        float adst_h = __shfl_sync(FULL, adst_l, hd4);

        // ---- pass 2: weighted gather ----
        for (int j = 0; j < deg; j++) {
            int s = g_nbr[base + j];                          // uniform -> broadcast
            float li = lrelu(__ldg(&asrc[s * HEADS + hd4]) + adst_h);
            float coef = __expf(li) * rden_h;
            uint2 v = *(const uint2*)&hh[(size_t)s * DIM + c4];
            float2 f0 = __half22float2(*reinterpret_cast<__half2*>(&v.x));
            float2 f1 = __half22float2(*reinterpret_cast<__half2*>(&v.y));
            acc0 += coef * f0.x;
            acc1 += coef * f0.y;
            acc2 += coef * f1.x;
            acc3 += coef * f1.y;
        }
    }

    *(float4*)&out[(size_t)n * DIM + c4] = make_float4(acc0, acc1, acc2, acc3);
}

// ---------------- launch --------------------------------------------------------
extern "C" void kernel_launch(void* const* d_in, const int* in_sizes, int n_in,
                              void* d_out, int out_size) {
    const float* x        = (const float*)d_in[0];
    const int*   ei       = (const int*)d_in[1];
    const float* W_in     = (const float*)d_in[2];
    const float* a_src_in = (const float*)d_in[3];
    const float* a_dst_in = (const float*)d_in[4];
    const float* b_in     = (const float*)d_in[5];
    const float* W_out    = (const float*)d_in[6];
    const float* a_src_out= (const float*)d_in[7];
    const float* a_dst_out= (const float*)d_in[8];
    const float* b_out    = (const float*)d_in[9];
    float* out = (float*)d_out;

    float*  h_in;   float*  h_out;
    __half* h_in_h; __half* h_out_h;
    cudaGetSymbolAddress((void**)&h_in,    g_h_in);
    cudaGetSymbolAddress((void**)&h_out,   g_h_out);
    cudaGetSymbolAddress((void**)&h_in_h,  g_h_in_h);
    cudaGetSymbolAddress((void**)&h_out_h, g_h_out_h);

    // CSR build (independent of GEMM results)
    zero_cnt_kernel<<<(NN2 + 255) / 256, 256>>>();
    hist_kernel<<<(EE + 255) / 256, 256>>>(ei);
    scan1_kernel<<<NB_SCAN, 256>>>();
    scan2_kernel<<<1, 128>>>();
    scan3_kernel<<<(NN2 + 255) / 256, 256>>>();
    scatter_kernel<<<(EE + 255) / 256, 256>>>(ei);

    // projections (fp32 + fp16 copies)
    gemm128_kernel<<<(NN + 127) / 128, 256>>>(x, W_in,  h_in,  h_in_h,  NN);
    gemm128_kernel<<<(NN + 127) / 128, 256>>>(x, W_out, h_out, h_out_h, NN);

    // per-node logits
    alpha_kernel<<<(NN * HEADS + 255) / 256, 256>>>(a_src_in, a_dst_in, a_src_out, a_dst_out);

    // gather-side aggregation (warp per node, both directions, bias folded in)
    agg_kernel<<<(NN * 32 + 255) / 256, 256>>>(out, b_in, b_out);
}

// round 6
// speedup vs baseline: 2.0736x; 1.3910x over previous
#include <cuda_runtime.h>
#include <cuda_fp16.h>
#include <cstdint>

#define NN 100000
#define EE 800000
#define HEADS 8
#define CH 16
#define DIM 128
#define NEG_SLOPE 0.2f

#define NN2 (2 * NN)
#define SCAN_CHUNK 2048
#define NB_SCAN ((NN2 + SCAN_CHUNK - 1) / SCAN_CHUNK)   // 98

// ---------------- scratch (device globals) --------------------------------------
__device__ __half g_h_in_h[NN * DIM];
__device__ __half g_h_out_h[NN * DIM];
__device__ float  g_asrc_in[NN * HEADS];
__device__ float  g_adst_in[NN * HEADS];
__device__ float  g_asrc_out[NN * HEADS];
__device__ float  g_adst_out[NN * HEADS];
__device__ float  g_WA[DIM * 32];          // [k][j]: j = 4 mats x 8 heads

__device__ int    g_cnt[NN2];
__device__ int    g_cur[NN2];
__device__ int    g_off[NN2 + 1];
__device__ int    g_bsum[128];
__device__ int    g_nbr[2 * EE];

// ---------------- helpers ------------------------------------------------------
__device__ __forceinline__ float lrelu(float v) {
    return v > 0.0f ? v : NEG_SLOPE * v;
}

__device__ __forceinline__ void ldsm_x4(uint32_t addr, uint32_t& r0, uint32_t& r1,
                                        uint32_t& r2, uint32_t& r3) {
    asm volatile("ldmatrix.sync.aligned.m8n8.x4.shared.b16 {%0,%1,%2,%3}, [%4];"
                 : "=r"(r0), "=r"(r1), "=r"(r2), "=r"(r3) : "r"(addr));
}
__device__ __forceinline__ void ldsm_x4_t(uint32_t addr, uint32_t& r0, uint32_t& r1,
                                          uint32_t& r2, uint32_t& r3) {
    asm volatile("ldmatrix.sync.aligned.m8n8.x4.trans.shared.b16 {%0,%1,%2,%3}, [%4];"
                 : "=r"(r0), "=r"(r1), "=r"(r2), "=r"(r3) : "r"(addr));
}
__device__ __forceinline__ void mma16816(float* c, const uint32_t* a, const uint32_t* b) {
    asm volatile(
        "mma.sync.aligned.m16n8k16.row.col.f32.f16.f16.f32 "
        "{%0,%1,%2,%3},{%4,%5,%6,%7},{%8,%9},{%10,%11,%12,%13};"
        : "=f"(c[0]), "=f"(c[1]), "=f"(c[2]), "=f"(c[3])
        : "r"(a[0]), "r"(a[1]), "r"(a[2]), "r"(a[3]), "r"(b[0]), "r"(b[1]),
          "f"(c[0]), "f"(c[1]), "f"(c[2]), "f"(c[3]));
}

// ---------------- CSR build ----------------------------------------------------
__global__ void zero_cnt_kernel() {
    int t = blockIdx.x * blockDim.x + threadIdx.x;
    if (t < NN2) { g_cnt[t] = 0; g_cur[t] = 0; }
}

__global__ void hist_kernel(const int* __restrict__ ei) {
    int e = blockIdx.x * blockDim.x + threadIdx.x;
    if (e >= EE) return;
    int s = __ldg(&ei[e]);
    int d = __ldg(&ei[EE + e]);
    atomicAdd(&g_cnt[d], 1);
    atomicAdd(&g_cnt[NN + s], 1);
}

__global__ void scan1_kernel() {
    __shared__ int sh[256];
    int b = blockIdx.x;
    int t = threadIdx.x;
    int base = b * SCAN_CHUNK + t * 8;
    int v[8];
    int s = 0;
#pragma unroll
    for (int k = 0; k < 8; k++) {
        int idx = base + k;
        v[k] = (idx < NN2) ? g_cnt[idx] : 0;
        s += v[k];
    }
    sh[t] = s;
    __syncthreads();
#pragma unroll
    for (int off = 1; off < 256; off <<= 1) {
        int x = (t >= off) ? sh[t - off] : 0;
        __syncthreads();
        if (t >= off) sh[t] += x;
        __syncthreads();
    }
    int excl = sh[t] - s;
    if (t == 255) g_bsum[b] = sh[t];
    int run = excl;
#pragma unroll
    for (int k = 0; k < 8; k++) {
        int idx = base + k;
        if (idx < NN2) g_off[idx] = run;
        run += v[k];
    }
}

__global__ void scan2_kernel() {
    __shared__ int sh[128];
    int t = threadIdx.x;
    int s = (t < NB_SCAN) ? g_bsum[t] : 0;
    sh[t] = s;
    __syncthreads();
#pragma unroll
    for (int off = 1; off < 128; off <<= 1) {
        int x = (t >= off) ? sh[t - off] : 0;
        __syncthreads();
        if (t >= off) sh[t] += x;
        __syncthreads();
    }
    g_bsum[t] = sh[t] - s;
}

__global__ void scan3_kernel() {
    int t = blockIdx.x * blockDim.x + threadIdx.x;
    if (t < NN2) g_off[t] += g_bsum[t / SCAN_CHUNK];
    if (t == 0) g_off[NN2] = 2 * EE;
}

__global__ void scatter_kernel(const int* __restrict__ ei) {
    int e = blockIdx.x * blockDim.x + threadIdx.x;
    if (e >= EE) return;
    int s = __ldg(&ei[e]);
    int d = __ldg(&ei[EE + e]);
    int p0 = g_off[d] + atomicAdd(&g_cur[d], 1);
    g_nbr[p0] = s;
    int p1 = g_off[NN + s] + atomicAdd(&g_cur[NN + s], 1);
    g_nbr[p1] = d;
}

// ---------------- WA = W @ A precompute (exact, tiny) ---------------------------
__global__ void wa_kernel(const float* __restrict__ W_in,  const float* __restrict__ W_out,
                          const float* __restrict__ asi,   const float* __restrict__ adi,
                          const float* __restrict__ aso,   const float* __restrict__ ado) {
    int t = blockIdx.x * blockDim.x + threadIdx.x;
    if (t >= DIM * 32) return;
    int k = t >> 5;
    int j = t & 31;
    int mat = j >> 3;
    int h = j & 7;
    const float* W  = (mat < 2) ? W_in : W_out;
    const float* av = (mat == 0) ? asi : (mat == 1) ? adi : (mat == 2) ? aso : ado;
    float s = 0.f;
#pragma unroll
    for (int c = 0; c < CH; c++)
        s += W[k * DIM + h * CH + c] * av[h * CH + c];
    g_WA[k * 32 + j] = s;
}

// ---------------- alphas = x @ WA (exact fp32, skinny GEMM) ---------------------
__global__ __launch_bounds__(256)
void alpha4_kernel(const float* __restrict__ x) {
    __shared__ float xs[32][132];
    __shared__ float was[DIM][32];
    int t = threadIdx.x;
    int n0 = blockIdx.x * 32;

#pragma unroll
    for (int i = 0; i < 16; i++) {
        int idx = i * 256 + t;
        was[idx >> 5][idx & 31] = g_WA[idx];
    }
#pragma unroll
    for (int i = 0; i < 4; i++) {
        int idx = i * 256 + t;
        int row = idx >> 5;
        int c4 = idx & 31;
        float4 v = make_float4(0.f, 0.f, 0.f, 0.f);
        if (n0 + row < NN) v = *(const float4*)&x[(size_t)(n0 + row) * DIM + c4 * 4];
        *(float4*)&xs[row][c4 * 4] = v;
    }
    __syncthreads();

    int n_loc = t >> 3;
    int pair = t & 7;
    int j0 = pair * 4;
    float a0 = 0.f, a1 = 0.f, a2 = 0.f, a3 = 0.f;
#pragma unroll
    for (int k = 0; k < DIM; k++) {
        float xv = xs[n_loc][k];
        float4 w = *(const float4*)&was[k][j0];
        a0 += xv * w.x;
        a1 += xv * w.y;
        a2 += xv * w.z;
        a3 += xv * w.w;
    }
    int n = n0 + n_loc;
    if (n < NN) {
        int mat = pair >> 1;
        int hb = (pair & 1) * 4;
        float* p = (mat == 0) ? g_asrc_in : (mat == 1) ? g_adst_in
                 : (mat == 2) ? g_asrc_out : g_adst_out;
        *(float4*)&p[n * HEADS + hb] = make_float4(a0, a1, a2, a3);
    }
}

// ---------------- HMMA projection: Ch[M,128] = fp16(A[M,128] @ B[128,128]) ------
// 256 thr = 8 warps; warp w -> rows m0=(w>>1)*32, cols n0=(w&1)*64.
// BK=64, swizzled fp16 smem tiles, ldmatrix + mma.m16n8k16.
__global__ __launch_bounds__(256)
void gemm_hmma_kernel(const float* __restrict__ A, const float* __restrict__ B,
                      __half* __restrict__ Ch, int M) {
    __shared__ __align__(16) char sA[128 * 64 * 2];   // 16 KB
    __shared__ __align__(16) char sB[64 * 128 * 2];   // 16 KB

    int t = threadIdx.x;
    int w = t >> 5;
    int lane = t & 31;
    int row0 = blockIdx.x * 128;
    int m0 = (w >> 1) * 32;
    int n0 = (w & 1) * 64;

    uint32_t baseA = (uint32_t)__cvta_generic_to_shared(sA);
    uint32_t baseB = (uint32_t)__cvta_generic_to_shared(sB);

    float c[2][8][4];
#pragma unroll
    for (int mi = 0; mi < 2; mi++)
#pragma unroll
        for (int ni = 0; ni < 8; ni++)
#pragma unroll
            for (int q = 0; q < 4; q++) c[mi][ni][q] = 0.f;

    for (int kk0 = 0; kk0 < DIM; kk0 += 64) {
        // load A tile [128 x 64] fp32 -> fp16, swizzled
#pragma unroll
        for (int i = 0; i < 8; i++) {
            int idx = i * 256 + t;      // 0..2047
            int row = idx >> 4;
            int c4 = idx & 15;
            float4 v = make_float4(0.f, 0.f, 0.f, 0.f);
            if (row0 + row < M)
                v = *(const float4*)&A[(size_t)(row0 + row) * DIM + kk0 + c4 * 4];
            __half2 h0 = __floats2half2_rn(v.x, v.y);
            __half2 h1 = __floats2half2_rn(v.z, v.w);
            int swz = (c4 >> 1) ^ (row & 7);
            uint2* p = (uint2*)(sA + row * 128 + swz * 16 + (c4 & 1) * 8);
            *p = make_uint2(*(unsigned*)&h0, *(unsigned*)&h1);
        }
        // load B tile [64 x 128]
#pragma unroll
        for (int i = 0; i < 8; i++) {
            int idx = i * 256 + t;
            int row = idx >> 5;
            int c4 = idx & 31;
            float4 v = *(const float4*)&B[(size_t)(kk0 + row) * DIM + c4 * 4];
            __half2 h0 = __floats2half2_rn(v.x, v.y);
            __half2 h1 = __floats2half2_rn(v.z, v.w);
            int swz = (c4 >> 1) ^ (row & 7);
            uint2* p = (uint2*)(sB + row * 256 + swz * 16 + (c4 & 1) * 8);
            *p = make_uint2(*(unsigned*)&h0, *(unsigned*)&h1);
        }
        __syncthreads();

#pragma unroll
        for (int ks = 0; ks < 4; ks++) {
            uint32_t a[2][4];
#pragma unroll
            for (int mi = 0; mi < 2; mi++) {
                int row = m0 + mi * 16 + (lane & 15);
                int chunk = ks * 2 + (lane >> 4);
                int swz = chunk ^ (row & 7);
                ldsm_x4(baseA + row * 128 + swz * 16,
                        a[mi][0], a[mi][1], a[mi][2], a[mi][3]);
            }
            uint32_t b[4][4];
#pragma unroll
            for (int np = 0; np < 4; np++) {
                int row = ks * 16 + (lane & 15);
                int chunk = (n0 >> 3) + np * 2 + (lane >> 4);
                int swz = chunk ^ (row & 7);
                ldsm_x4_t(baseB + row * 256 + swz * 16,
                          b[np][0], b[np][1], b[np][2], b[np][3]);
            }
#pragma unroll
            for (int mi = 0; mi < 2; mi++)
#pragma unroll
                for (int ni = 0; ni < 8; ni++)
                    mma16816(c[mi][ni], a[mi], &b[ni >> 1][(ni & 1) * 2]);
        }
        __syncthreads();
    }

    // epilogue: fp16 stores
    int gid = lane >> 2;
    int qq = lane & 3;
#pragma unroll
    for (int mi = 0; mi < 2; mi++) {
#pragma unroll
        for (int ni = 0; ni < 8; ni++) {
            int row = row0 + m0 + mi * 16 + gid;
            int col = n0 + ni * 8 + qq * 2;
            if (row < M) {
                __half2 hv = __floats2half2_rn(c[mi][ni][0], c[mi][ni][1]);
                *(__half2*)&Ch[(size_t)row * DIM + col] = hv;
            }
            if (row + 8 < M) {
                __half2 hv = __floats2half2_rn(c[mi][ni][2], c[mi][ni][3]);
                *(__half2*)&Ch[(size_t)(row + 8) * DIM + col] = hv;
            }
        }
    }
}

// ---------------- aggregation: warp per node, gather-side -----------------------
__global__ __launch_bounds__(256)
void agg_kernel(float* __restrict__ out,
                const float* __restrict__ b_in,
                const float* __restrict__ b_out) {
    int w = (blockIdx.x * blockDim.x + threadIdx.x) >> 5;
    if (w >= NN) return;
    int n = w;
    int lane = threadIdx.x & 31;
    unsigned FULL = 0xFFFFFFFFu;

    int c4 = lane * 4;
    int hd4 = lane >> 2;
    int hd8 = lane & 7;

    float4 bi = *(const float4*)&b_in[c4];
    float4 bo = *(const float4*)&b_out[c4];
    float acc0 = bi.x + bo.x, acc1 = bi.y + bo.y;
    float acc2 = bi.z + bo.z, acc3 = bi.w + bo.w;

#pragma unroll
    for (int dir = 0; dir < 2; dir++) {
        const float*  asrc = dir ? g_asrc_out : g_asrc_in;
        const float*  adst = dir ? g_adst_out : g_adst_in;
        const __half* hh   = dir ? g_h_out_h  : g_h_in_h;

        int base = g_off[dir * NN + n];
        int deg  = g_off[dir * NN + n + 1] - base;

        float adst_l = adst[n * HEADS + hd8];
        float den = 0.0f;
        for (int j = (lane >> 3); j < deg; j += 4) {
            int s = g_nbr[base + j];
            float li = lrelu(__ldg(&asrc[s * HEADS + hd8]) + adst_l);
            den += __expf(li);
        }
        den += __shfl_xor_sync(FULL, den, 8);
        den += __shfl_xor_sync(FULL, den, 16);
        float rden = __frcp_rn(den);

        float rden_h = __shfl_sync(FULL, rden, hd4);
        float adst_h = __shfl_sync(FULL, adst_l, hd4);

        for (int j = 0; j < deg; j++) {
            int s = g_nbr[base + j];
            float li = lrelu(__ldg(&asrc[s * HEADS + hd4]) + adst_h);
            float coef = __expf(li) * rden_h;
            uint2 v = *(const uint2*)&hh[(size_t)s * DIM + c4];
            float2 f0 = __half22float2(*reinterpret_cast<__half2*>(&v.x));
            float2 f1 = __half22float2(*reinterpret_cast<__half2*>(&v.y));
            acc0 += coef * f0.x;
            acc1 += coef * f0.y;
            acc2 += coef * f1.x;
            acc3 += coef * f1.y;
        }
    }

    *(float4*)&out[(size_t)n * DIM + c4] = make_float4(acc0, acc1, acc2, acc3);
}

// ---------------- launch --------------------------------------------------------
extern "C" void kernel_launch(void* const* d_in, const int* in_sizes, int n_in,
                              void* d_out, int out_size) {
    const float* x        = (const float*)d_in[0];
    const int*   ei       = (const int*)d_in[1];
    const float* W_in     = (const float*)d_in[2];
    const float* a_src_in = (const float*)d_in[3];
    const float* a_dst_in = (const float*)d_in[4];
    const float* b_in     = (const float*)d_in[5];
    const float* W_out    = (const float*)d_in[6];
    const float* a_src_out= (const float*)d_in[7];
    const float* a_dst_out= (const float*)d_in[8];
    const float* b_out    = (const float*)d_in[9];
    float* out = (float*)d_out;

    __half* h_in_h;
    __half* h_out_h;
    cudaGetSymbolAddress((void**)&h_in_h,  g_h_in_h);
    cudaGetSymbolAddress((void**)&h_out_h, g_h_out_h);

    // CSR build
    zero_cnt_kernel<<<(NN2 + 255) / 256, 256>>>();
    hist_kernel<<<(EE + 255) / 256, 256>>>(ei);
    scan1_kernel<<<NB_SCAN, 256>>>();
    scan2_kernel<<<1, 128>>>();
    scan3_kernel<<<(NN2 + 255) / 256, 256>>>();
    scatter_kernel<<<(EE + 255) / 256, 256>>>(ei);

    // exact alphas: WA then x @ WA
    wa_kernel<<<(DIM * 32 + 255) / 256, 256>>>(W_in, W_out, a_src_in, a_dst_in,
                                               a_src_out, a_dst_out);
    alpha4_kernel<<<(NN + 31) / 32, 256>>>(x);

    // fp16 tensor-core projections
    gemm_hmma_kernel<<<(NN + 127) / 128, 256>>>(x, W_in,  h_in_h,  NN);
    gemm_hmma_kernel<<<(NN + 127) / 128, 256>>>(x, W_out, h_out_h, NN);

    // gather-side aggregation
    agg_kernel<<<(NN * 32 + 255) / 256, 256>>>(out, b_in, b_out);
}

// round 7
// speedup vs baseline: 2.9496x; 1.4224x over previous
#include <cuda_runtime.h>
#include <cuda_fp16.h>
#include <cstdint>

#define NN 100000
#define EE 800000
#define HEADS 8
#define CH 16
#define DIM 128
#define NEG_SLOPE 0.2f

#define NN2 (2 * NN)
#define SCAN_CHUNK 2048
#define NB_SCAN ((NN2 + SCAN_CHUNK - 1) / SCAN_CHUNK)   // 98

// ---------------- scratch (device globals) --------------------------------------
__device__ __half g_h_in_h[NN * DIM];
__device__ __half g_h_out_h[NN * DIM];
__device__ float  g_asrc_in[NN * HEADS];
__device__ float  g_adst_in[NN * HEADS];
__device__ float  g_asrc_out[NN * HEADS];
__device__ float  g_adst_out[NN * HEADS];

__device__ int    g_cnt[NN2];
__device__ int    g_cur[NN2];
__device__ int    g_off[NN2 + 1];
__device__ int    g_bsum[128];
__device__ int    g_nbr[2 * EE];

// ---------------- helpers ------------------------------------------------------
__device__ __forceinline__ float lrelu(float v) {
    return v > 0.0f ? v : NEG_SLOPE * v;
}

__device__ __forceinline__ void ldsm_x4(uint32_t addr, uint32_t& r0, uint32_t& r1,
                                        uint32_t& r2, uint32_t& r3) {
    asm volatile("ldmatrix.sync.aligned.m8n8.x4.shared.b16 {%0,%1,%2,%3}, [%4];"
                 : "=r"(r0), "=r"(r1), "=r"(r2), "=r"(r3) : "r"(addr));
}
__device__ __forceinline__ void ldsm_x4_t(uint32_t addr, uint32_t& r0, uint32_t& r1,
                                          uint32_t& r2, uint32_t& r3) {
    asm volatile("ldmatrix.sync.aligned.m8n8.x4.trans.shared.b16 {%0,%1,%2,%3}, [%4];"
                 : "=r"(r0), "=r"(r1), "=r"(r2), "=r"(r3) : "r"(addr));
}
__device__ __forceinline__ void mma16816(float* c, const uint32_t* a, const uint32_t* b) {
    asm volatile(
        "mma.sync.aligned.m16n8k16.row.col.f32.f16.f16.f32 "
        "{%0,%1,%2,%3},{%4,%5,%6,%7},{%8,%9},{%10,%11,%12,%13};"
        : "=f"(c[0]), "=f"(c[1]), "=f"(c[2]), "=f"(c[3])
        : "r"(a[0]), "r"(a[1]), "r"(a[2]), "r"(a[3]), "r"(b[0]), "r"(b[1]),
          "f"(c[0]), "f"(c[1]), "f"(c[2]), "f"(c[3]));
}

// ---------------- CSR build ----------------------------------------------------
__global__ void zero_cnt_kernel() {
    int t = blockIdx.x * blockDim.x + threadIdx.x;
    if (t < NN2) { g_cnt[t] = 0; g_cur[t] = 0; }
}

__global__ void hist_kernel(const int* __restrict__ ei) {
    int e = blockIdx.x * blockDim.x + threadIdx.x;
    if (e >= EE) return;
    int s = __ldg(&ei[e]);
    int d = __ldg(&ei[EE + e]);
    atomicAdd(&g_cnt[d], 1);
    atomicAdd(&g_cnt[NN + s], 1);
}

__global__ void scan1_kernel() {
    __shared__ int sh[256];
    int b = blockIdx.x;
    int t = threadIdx.x;
    int base = b * SCAN_CHUNK + t * 8;
    int v[8];
    int s = 0;
#pragma unroll
    for (int k = 0; k < 8; k++) {
        int idx = base + k;
        v[k] = (idx < NN2) ? g_cnt[idx] : 0;
        s += v[k];
    }
    sh[t] = s;
    __syncthreads();
#pragma unroll
    for (int off = 1; off < 256; off <<= 1) {
        int x = (t >= off) ? sh[t - off] : 0;
        __syncthreads();
        if (t >= off) sh[t] += x;
        __syncthreads();
    }
    int excl = sh[t] - s;
    if (t == 255) g_bsum[b] = sh[t];
    int run = excl;
#pragma unroll
    for (int k = 0; k < 8; k++) {
        int idx = base + k;
        if (idx < NN2) g_off[idx] = run;
        run += v[k];
    }
}

__global__ void scan2_kernel() {
    __shared__ int sh[128];
    int t = threadIdx.x;
    int s = (t < NB_SCAN) ? g_bsum[t] : 0;
    sh[t] = s;
    __syncthreads();
#pragma unroll
    for (int off = 1; off < 128; off <<= 1) {
        int x = (t >= off) ? sh[t - off] : 0;
        __syncthreads();
        if (t >= off) sh[t] += x;
        __syncthreads();
    }
    g_bsum[t] = sh[t] - s;
}

__global__ void scan3_kernel() {
    int t = blockIdx.x * blockDim.x + threadIdx.x;
    if (t < NN2) g_off[t] += g_bsum[t / SCAN_CHUNK];
    if (t == 0) g_off[NN2] = 2 * EE;
}

__global__ void scatter_kernel(const int* __restrict__ ei) {
    int e = blockIdx.x * blockDim.x + threadIdx.x;
    if (e >= EE) return;
    int s = __ldg(&ei[e]);
    int d = __ldg(&ei[EE + e]);
    int p0 = g_off[d] + atomicAdd(&g_cur[d], 1);
    g_nbr[p0] = s;
    int p1 = g_off[NN + s] + atomicAdd(&g_cur[NN + s], 1);
    g_nbr[p1] = d;
}

// ---------------- fused projection GEMM + alpha epilogue ------------------------
// 512 threads = 16 warps. mat = warp>>3 selects {W_in, W_out}.
// Within a mat: 8 warps tile 128 rows x 128 cols (warp: 32 rows x 64 cols).
// Epilogue: fp16 h store + exact alpha dot from fp32 accumulators.
__global__ __launch_bounds__(512)
void gemm_fused_kernel(const float* __restrict__ A,
                       const float* __restrict__ Win, const float* __restrict__ Wout,
                       const float* __restrict__ asi, const float* __restrict__ adi,
                       const float* __restrict__ aso, const float* __restrict__ ado,
                       int M) {
    __shared__ __align__(16) char sA[128 * 64 * 2];        // 16 KB
    __shared__ __align__(16) char sB[2][64 * 128 * 2];     // 2 x 16 KB

    int t = threadIdx.x;
    int w = t >> 5;
    int lane = t & 31;
    int mat = w >> 3;
    int w8 = w & 7;
    int m0 = (w8 >> 1) * 32;
    int n0 = (w8 & 1) * 64;
    int row0 = blockIdx.x * 128;

    uint32_t baseA = (uint32_t)__cvta_generic_to_shared(sA);
    uint32_t baseB = (uint32_t)__cvta_generic_to_shared(sB[mat]);

    float c[2][8][4];
#pragma unroll
    for (int mi = 0; mi < 2; mi++)
#pragma unroll
        for (int ni = 0; ni < 8; ni++)
#pragma unroll
            for (int q = 0; q < 4; q++) c[mi][ni][q] = 0.f;

    for (int kk0 = 0; kk0 < DIM; kk0 += 64) {
        // A tile [128 x 64] fp32 -> fp16, swizzled (2048 uint2, 4 per thread)
#pragma unroll
        for (int i = 0; i < 4; i++) {
            int idx = i * 512 + t;
            int row = idx >> 4;
            int c4 = idx & 15;
            float4 v = make_float4(0.f, 0.f, 0.f, 0.f);
            if (row0 + row < M)
                v = *(const float4*)&A[(size_t)(row0 + row) * DIM + kk0 + c4 * 4];
            __half2 h0 = __floats2half2_rn(v.x, v.y);
            __half2 h1 = __floats2half2_rn(v.z, v.w);
            int swz = (c4 >> 1) ^ (row & 7);
            uint2* p = (uint2*)(sA + row * 128 + swz * 16 + (c4 & 1) * 8);
            *p = make_uint2(*(unsigned*)&h0, *(unsigned*)&h1);
        }
        // B tiles [64 x 128] for both mats
#pragma unroll
        for (int m = 0; m < 2; m++) {
            const float* B = m ? Wout : Win;
#pragma unroll
            for (int i = 0; i < 4; i++) {
                int idx = i * 512 + t;
                int row = idx >> 5;
                int c4 = idx & 31;
                float4 v = *(const float4*)&B[(size_t)(kk0 + row) * DIM + c4 * 4];
                __half2 h0 = __floats2half2_rn(v.x, v.y);
                __half2 h1 = __floats2half2_rn(v.z, v.w);
                int swz = (c4 >> 1) ^ (row & 7);
                uint2* p = (uint2*)(sB[m] + row * 256 + swz * 16 + (c4 & 1) * 8);
                *p = make_uint2(*(unsigned*)&h0, *(unsigned*)&h1);
            }
        }
        __syncthreads();

#pragma unroll
        for (int ks = 0; ks < 4; ks++) {
            uint32_t a[2][4];
#pragma unroll
            for (int mi = 0; mi < 2; mi++) {
                int row = m0 + mi * 16 + (lane & 15);
                int chunk = ks * 2 + (lane >> 4);
                int swz = chunk ^ (row & 7);
                ldsm_x4(baseA + row * 128 + swz * 16,
                        a[mi][0], a[mi][1], a[mi][2], a[mi][3]);
            }
            uint32_t b[4][4];
#pragma unroll
            for (int np = 0; np < 4; np++) {
                int row = ks * 16 + (lane & 15);
                int chunk = (n0 >> 3) + np * 2 + (lane >> 4);
                int swz = chunk ^ (row & 7);
                ldsm_x4_t(baseB + row * 256 + swz * 16,
                          b[np][0], b[np][1], b[np][2], b[np][3]);
            }
#pragma unroll
            for (int mi = 0; mi < 2; mi++)
#pragma unroll
                for (int ni = 0; ni < 8; ni++)
                    mma16816(c[mi][ni], a[mi], &b[ni >> 1][(ni & 1) * 2]);
        }
        __syncthreads();
    }

    // ---- epilogue 1: fp16 h stores ----
    __half* Ch = mat ? g_h_out_h : g_h_in_h;
    int gid = lane >> 2;
    int qq = lane & 3;
#pragma unroll
    for (int mi = 0; mi < 2; mi++) {
#pragma unroll
        for (int ni = 0; ni < 8; ni++) {
            int row = row0 + m0 + mi * 16 + gid;
            int col = n0 + ni * 8 + qq * 2;
            if (row < M) {
                __half2 hv = __floats2half2_rn(c[mi][ni][0], c[mi][ni][1]);
                *(__half2*)&Ch[(size_t)row * DIM + col] = hv;
            }
            if (row + 8 < M) {
                __half2 hv = __floats2half2_rn(c[mi][ni][2], c[mi][ni][3]);
                *(__half2*)&Ch[(size_t)(row + 8) * DIM + col] = hv;
            }
        }
    }

    // ---- epilogue 2: alpha logits (exact dot of fp32 acc with a-vectors) ----
    const float* av_s = mat ? aso : asi;   // flattened [h*16+c] = [col]
    const float* av_d = mat ? ado : adi;
    float* p_src = mat ? g_asrc_out : g_asrc_in;
    float* p_dst = mat ? g_adst_out : g_adst_in;
    int hb = (w8 & 1) * 4;                 // this warp's 4 heads

#pragma unroll
    for (int mi = 0; mi < 2; mi++) {
        float ps[2][4], pd[2][4];
#pragma unroll
        for (int r = 0; r < 2; r++)
#pragma unroll
            for (int hl = 0; hl < 4; hl++) { ps[r][hl] = 0.f; pd[r][hl] = 0.f; }
#pragma unroll
        for (int ni = 0; ni < 8; ni++) {
            int col = n0 + ni * 8 + qq * 2;
            float s0 = __ldg(&av_s[col]), s1 = __ldg(&av_s[col + 1]);
            float d0 = __ldg(&av_d[col]), d1 = __ldg(&av_d[col + 1]);
            int hl = ni >> 1;
            ps[0][hl] += c[mi][ni][0] * s0 + c[mi][ni][1] * s1;
            ps[1][hl] += c[mi][ni][2] * s0 + c[mi][ni][3] * s1;
            pd[0][hl] += c[mi][ni][0] * d0 + c[mi][ni][1] * d1;
            pd[1][hl] += c[mi][ni][2] * d0 + c[mi][ni][3] * d1;
        }
        // reduce across the 4 quad lanes (lane ^= 1, lane ^= 2)
#pragma unroll
        for (int r = 0; r < 2; r++)
#pragma unroll
            for (int hl = 0; hl < 4; hl++) {
                ps[r][hl] += __shfl_xor_sync(0xFFFFFFFFu, ps[r][hl], 1);
                ps[r][hl] += __shfl_xor_sync(0xFFFFFFFFu, ps[r][hl], 2);
                pd[r][hl] += __shfl_xor_sync(0xFFFFFFFFu, pd[r][hl], 1);
                pd[r][hl] += __shfl_xor_sync(0xFFFFFFFFu, pd[r][hl], 2);
            }
        if (qq == 0) {
#pragma unroll
            for (int r = 0; r < 2; r++) {
                int row = row0 + m0 + mi * 16 + gid + r * 8;
                if (row < M) {
                    *(float4*)&p_src[row * HEADS + hb] =
                        make_float4(ps[r][0], ps[r][1], ps[r][2], ps[r][3]);
                    *(float4*)&p_dst[row * HEADS + hb] =
                        make_float4(pd[r][0], pd[r][1], pd[r][2], pd[r][3]);
                }
            }
        }
    }
}

// ---------------- aggregation: warp per node, fused num/den single pass ---------
__global__ __launch_bounds__(256)
void agg_kernel(float* __restrict__ out,
                const float* __restrict__ b_in,
                const float* __restrict__ b_out) {
    int w = (blockIdx.x * blockDim.x + threadIdx.x) >> 5;
    if (w >= NN) return;
    int n = w;
    int lane = threadIdx.x & 31;
    int c4 = lane * 4;
    int hd = lane >> 2;

    float4 bi = *(const float4*)&b_in[c4];
    float4 bo = *(const float4*)&b_out[c4];
    float o0 = bi.x + bo.x, o1 = bi.y + bo.y;
    float o2 = bi.z + bo.z, o3 = bi.w + bo.w;

#pragma unroll
    for (int dir = 0; dir < 2; dir++) {
        const float*  asrc = dir ? g_asrc_out : g_asrc_in;
        const float*  adst = dir ? g_adst_out : g_adst_in;
        const __half* hh   = dir ? g_h_out_h  : g_h_in_h;

        int base = g_off[dir * NN + n];
        int deg  = g_off[dir * NN + n + 1] - base;
        float adst_l = __ldg(&adst[n * HEADS + hd]);

        float den = 0.f;
        float a0 = 0.f, a1 = 0.f, a2 = 0.f, a3 = 0.f;
        for (int j = 0; j < deg; j++) {
            int s = __ldg(&g_nbr[base + j]);
            float li = lrelu(__ldg(&asrc[s * HEADS + hd]) + adst_l);
            float p = __expf(li);
            uint2 v = *(const uint2*)&hh[(size_t)s * DIM + c4];
            float2 f0 = __half22float2(*reinterpret_cast<__half2*>(&v.x));
            float2 f1 = __half22float2(*reinterpret_cast<__half2*>(&v.y));
            den += p;
            a0 += p * f0.x;
            a1 += p * f0.y;
            a2 += p * f1.x;
            a3 += p * f1.y;
        }
        float r = (deg > 0) ? __frcp_rn(den) : 0.f;
        o0 += a0 * r;
        o1 += a1 * r;
        o2 += a2 * r;
        o3 += a3 * r;
    }

    *(float4*)&out[(size_t)n * DIM + c4] = make_float4(o0, o1, o2, o3);
}

// ---------------- launch --------------------------------------------------------
extern "C" void kernel_launch(void* const* d_in, const int* in_sizes, int n_in,
                              void* d_out, int out_size) {
    const float* x        = (const float*)d_in[0];
    const int*   ei       = (const int*)d_in[1];
    const float* W_in     = (const float*)d_in[2];
    const float* a_src_in = (const float*)d_in[3];
    const float* a_dst_in = (const float*)d_in[4];
    const float* b_in     = (const float*)d_in[5];
    const float* W_out    = (const float*)d_in[6];
    const float* a_src_out= (const float*)d_in[7];
    const float* a_dst_out= (const float*)d_in[8];
    const float* b_out    = (const float*)d_in[9];
    float* out = (float*)d_out;

    // CSR build
    zero_cnt_kernel<<<(NN2 + 255) / 256, 256>>>();
    hist_kernel<<<(EE + 255) / 256, 256>>>(ei);
    scan1_kernel<<<NB_SCAN, 256>>>();
    scan2_kernel<<<1, 128>>>();
    scan3_kernel<<<(NN2 + 255) / 256, 256>>>();
    scatter_kernel<<<(EE + 255) / 256, 256>>>(ei);

    // fused fp16 tensor-core projection (both weights) + alpha epilogue
    gemm_fused_kernel<<<(NN + 127) / 128, 512>>>(x, W_in, W_out,
                                                 a_src_in, a_dst_in,
                                                 a_src_out, a_dst_out, NN);

    // gather-side aggregation (single fused pass)
    agg_kernel<<<(NN * 32 + 255) / 256, 256>>>(out, b_in, b_out);
}